// round 3
// baseline (speedup 1.0000x reference)
#include <cuda_runtime.h>
#include <math.h>

#define NMAX 100000
#define EMAX 1600000
#define HDIM 128

// ---------------- scratch (device globals; referenced by name only) --------
__device__ __align__(16) float g_m [NMAX * HDIM];
__device__ __align__(16) float g_h1[NMAX * HDIM];
__device__ __align__(16) float g_h2[NMAX * HDIM];
__device__ __align__(16) float g_h3[NMAX * HDIM];
__device__ int   g_deg[NMAX];
__device__ int   g_off[NMAX + 1];
__device__ int   g_cur[NMAX];
__device__ int   g_csr[EMAX];
__device__ int   g_bsum[128];
__device__ __align__(16) float g_Wt[2 * HDIM * HDIM];  // [k][j], Wl rows 0..127, Wr rows 128..255

// device-side buffer selector (avoids cudaGetSymbolAddress on host)
__device__ __forceinline__ float* selbuf(int s) {
    switch (s) {
        case 1:  return g_h1;
        case 2:  return g_h2;
        case 3:  return g_h3;
        default: return g_m;
    }
}

// ---------------- CSR build ------------------------------------------------
__global__ void k_zero(int n) {
    int i = blockIdx.x * blockDim.x + threadIdx.x;
    if (i < n) { g_deg[i] = 0; g_cur[i] = 0; }
}

__global__ void k_hist(const int* __restrict__ ei, int E, int n) {
    int e = blockIdx.x * blockDim.x + threadIdx.x;
    if (e < E) {
        int d = ei[E + e];
        if ((unsigned)d < (unsigned)n) atomicAdd(&g_deg[d], 1);
    }
}

__global__ void k_scan1(int n) {
    __shared__ int s[1024];
    int tid = threadIdx.x;
    int gid = blockIdx.x * 1024 + tid;
    int v = (gid < n) ? g_deg[gid] : 0;
    s[tid] = v;
    __syncthreads();
    for (int d = 1; d < 1024; d <<= 1) {
        int t = (tid >= d) ? s[tid - d] : 0;
        __syncthreads();
        s[tid] += t;
        __syncthreads();
    }
    if (gid < n) g_off[gid] = s[tid] - v;           // exclusive
    if (tid == 1023) g_bsum[blockIdx.x] = s[1023];  // block total
}

__global__ void k_scan2(int nb) {
    if (threadIdx.x == 0 && blockIdx.x == 0) {
        int acc = 0;
        for (int i = 0; i < nb; i++) { int t = g_bsum[i]; g_bsum[i] = acc; acc += t; }
    }
}

__global__ void k_scan3(int n, int E) {
    int gid = blockIdx.x * blockDim.x + threadIdx.x;
    if (gid < n)       g_off[gid] += g_bsum[gid >> 10];
    else if (gid == n) g_off[n] = E;
}

__global__ void k_fill(const int* __restrict__ ei, int E, int n) {
    int e = blockIdx.x * blockDim.x + threadIdx.x;
    if (e < E) {
        int s = ei[e];
        int d = ei[E + e];
        if ((unsigned)s < (unsigned)n && (unsigned)d < (unsigned)n) {
            int pos = g_off[d] + atomicAdd(&g_cur[d], 1);
            if ((unsigned)pos < (unsigned)E) g_csr[pos] = s;
        }
    }
}

// ---------------- per-node max aggregation (warp per node) -----------------
// reads hext (if hsel<0) or selbuf(hsel); writes g_m
__global__ void k_agg(const float* __restrict__ hext, int hsel, int n) {
    const float* h = (hsel < 0) ? hext : selbuf(hsel);
    int w    = (blockIdx.x * blockDim.x + threadIdx.x) >> 5;
    int lane = threadIdx.x & 31;
    if (w >= n) return;
    int beg = g_off[w], end = g_off[w + 1];
    float4 mx = make_float4(0.f, 0.f, 0.f, 0.f);
    if (beg < end) {
        mx = make_float4(-INFINITY, -INFINITY, -INFINITY, -INFINITY);
        const float4* hv = (const float4*)h;
        int j = beg;
        for (; j + 1 < end; j += 2) {
            int s0 = g_csr[j], s1 = g_csr[j + 1];
            float4 v0 = hv[(long long)s0 * 32 + lane];
            float4 v1 = hv[(long long)s1 * 32 + lane];
            mx.x = fmaxf(mx.x, fmaxf(v0.x, v1.x));
            mx.y = fmaxf(mx.y, fmaxf(v0.y, v1.y));
            mx.z = fmaxf(mx.z, fmaxf(v0.z, v1.z));
            mx.w = fmaxf(mx.w, fmaxf(v0.w, v1.w));
        }
        if (j < end) {
            int s0 = g_csr[j];
            float4 v0 = hv[(long long)s0 * 32 + lane];
            mx.x = fmaxf(mx.x, v0.x);
            mx.y = fmaxf(mx.y, v0.y);
            mx.z = fmaxf(mx.z, v0.z);
            mx.w = fmaxf(mx.w, v0.w);
        }
    }
    ((float4*)g_m)[(long long)w * 32 + lane] = mx;
}

// ---------------- weight transpose into g_Wt -------------------------------
__global__ void k_transpose(const float* __restrict__ Wl,
                            const float* __restrict__ Wr) {
    int idx = blockIdx.x * blockDim.x + threadIdx.x;
    if (idx >= HDIM * HDIM) return;
    int j = idx >> 7, k = idx & 127;
    g_Wt[k * HDIM + j]          = Wl[idx];
    g_Wt[(k + HDIM) * HDIM + j] = Wr[idx];
}

// ---------------- fused layer GEMM + bias + ELU + residual -----------------
// out[i,:] = elu( m[i,:]@Wl^T + b + h[i,:]@Wr^T ) (+ res[i,:])
// one block = 128 nodes x 128 cols; K=256 streamed in 8 chunks of 32.
// static shared: Ws 16KB + Fs 16.5KB  (< 48KB, no attribute needed)
#define FS_STRIDE 132

__global__ void __launch_bounds__(256)
k_layer(const float* __restrict__ hext, int hsel,
        const float* __restrict__ bias, int ressel, int outsel, int n) {
    __shared__ float Ws[32 * 128];
    __shared__ float Fs[32 * FS_STRIDE];

    const float* h   = (hsel < 0)   ? hext : selbuf(hsel);
    const float* m   = g_m;
    const float* res = (ressel < 0) ? (const float*)0 : selbuf(ressel);
    float*       out = selbuf(outsel);

    const int tx = threadIdx.x;
    const int c  = tx & 15;   // col group: cols c*8 .. c*8+7
    const int r  = tx >> 4;   // row group: nodes r*8 .. r*8+7
    const int base = blockIdx.x * 128;

    float acc[8][8];
#pragma unroll
    for (int i = 0; i < 8; i++)
#pragma unroll
        for (int j = 0; j < 8; j++) acc[i][j] = 0.f;

    for (int kc = 0; kc < 8; kc++) {
        const float* src = (kc < 4) ? m : h;
        int k0 = (kc & 3) * 32;
        __syncthreads();
        // weights chunk: g_Wt rows kc*32 .. kc*32+31 (k-major, coalesced f4)
        {
            const float4* wsrc = (const float4*)(g_Wt + kc * 32 * 128);
            float4* wdst = (float4*)Ws;
#pragma unroll
            for (int rep = 0; rep < 4; rep++)
                wdst[rep * 256 + tx] = wsrc[rep * 256 + tx];
        }
        // feature chunk: Fs[k][node], global reads coalesced per node row
#pragma unroll
        for (int rep = 0; rep < 16; rep++) {
            int lin  = rep * 256 + tx;
            int k    = lin & 31;
            int node = lin >> 5;
            int gn   = base + node;
            float v  = 0.f;
            if (gn < n) v = src[(size_t)gn * HDIM + k0 + k];
            Fs[k * FS_STRIDE + node] = v;
        }
        __syncthreads();

#pragma unroll 8
        for (int k = 0; k < 32; k++) {
            float4 w0 = *(const float4*)&Ws[k * 128 + c * 8];
            float4 w1 = *(const float4*)&Ws[k * 128 + c * 8 + 4];
            float4 f0 = *(const float4*)&Fs[k * FS_STRIDE + r * 8];
            float4 f1 = *(const float4*)&Fs[k * FS_STRIDE + r * 8 + 4];
            float fv[8] = {f0.x, f0.y, f0.z, f0.w, f1.x, f1.y, f1.z, f1.w};
            float wv[8] = {w0.x, w0.y, w0.z, w0.w, w1.x, w1.y, w1.z, w1.w};
#pragma unroll
            for (int i = 0; i < 8; i++)
#pragma unroll
                for (int j = 0; j < 8; j++)
                    acc[i][j] += fv[i] * wv[j];
        }
    }

    // epilogue: bias + ELU + residual + store
    float bb[8];
#pragma unroll
    for (int j = 0; j < 8; j++) bb[j] = bias[c * 8 + j];

#pragma unroll
    for (int i = 0; i < 8; i++) {
        int gn = base + r * 8 + i;
        if (gn >= n) continue;
        size_t o = (size_t)gn * HDIM + c * 8;
        float v[8];
#pragma unroll
        for (int j = 0; j < 8; j++) {
            float t = acc[i][j] + bb[j];
            v[j] = (t > 0.f) ? t : expm1f(t);
        }
        if (res) {
            float4 r0 = *(const float4*)(res + o);
            float4 r1 = *(const float4*)(res + o + 4);
            v[0] += r0.x; v[1] += r0.y; v[2] += r0.z; v[3] += r0.w;
            v[4] += r1.x; v[5] += r1.y; v[6] += r1.z; v[7] += r1.w;
        }
        *(float4*)(out + o)     = make_float4(v[0], v[1], v[2], v[3]);
        *(float4*)(out + o + 4) = make_float4(v[4], v[5], v[6], v[7]);
    }
}

// ---------------- output head: sigmoid(h3 @ Wo^T + bo) ---------------------
__global__ void k_out(const float* __restrict__ Wo, const float* __restrict__ bo,
                      float* __restrict__ out, int n) {
    const float* h = g_h3;
    int w    = (blockIdx.x * blockDim.x + threadIdx.x) >> 5;
    int lane = threadIdx.x & 31;
    if (w >= n) return;
    float4 v  = ((const float4*)h)[(long long)w * 32 + lane];
    float4 wo = ((const float4*)Wo)[lane];
    float d = v.x * wo.x + v.y * wo.y + v.z * wo.z + v.w * wo.w;
#pragma unroll
    for (int o = 16; o > 0; o >>= 1) d += __shfl_xor_sync(0xffffffff, d, o);
    if (lane == 0) {
        float z = d + bo[0];
        out[w] = 1.f / (1.f + expf(-z));
    }
}

// ---------------- launcher (kernel launches ONLY) ---------------------------
extern "C" void kernel_launch(void* const* d_in, const int* in_sizes, int n_in,
                              void* d_out, int out_size) {
    const float* x   = (const float*)d_in[0];
    const int*   ei  = (const int*)d_in[1];     // edge_index is int32 (JAX x64 disabled)
    const float* W1l = (const float*)d_in[2];
    const float* b1  = (const float*)d_in[3];
    const float* W1r = (const float*)d_in[4];
    const float* W2l = (const float*)d_in[5];
    const float* b2  = (const float*)d_in[6];
    const float* W2r = (const float*)d_in[7];
    const float* W3l = (const float*)d_in[8];
    const float* b3  = (const float*)d_in[9];
    const float* W3r = (const float*)d_in[10];
    const float* Wo  = (const float*)d_in[11];
    const float* bo  = (const float*)d_in[12];
    float* out = (float*)d_out;

    int N = in_sizes[0] / HDIM;
    int E = in_sizes[1] / 2;
    if (N > NMAX) N = NMAX;
    if (E > EMAX) E = EMAX;

    // ---- CSR build (dst-sorted adjacency) ----
    k_zero <<<(N + 255) / 256, 256>>>(N);
    k_hist <<<(E + 255) / 256, 256>>>(ei, E, N);
    int nb = (N + 1023) / 1024;
    k_scan1<<<nb, 1024>>>(N);
    k_scan2<<<1, 32>>>(nb);
    k_scan3<<<(N + 1 + 1023) / 1024, 1024>>>(N, E);
    k_fill <<<(E + 255) / 256, 256>>>(ei, E, N);

    int aggBlocks   = (N * 32 + 255) / 256;
    int layerBlocks = (N + 127) / 128;

    // ---- layer 1: in x, out h1(sel 1), no residual ----
    k_agg      <<<aggBlocks, 256>>>(x, -1, N);
    k_transpose<<<64, 256>>>(W1l, W1r);
    k_layer    <<<layerBlocks, 256>>>(x, -1, b1, -1, 1, N);

    // ---- layer 2: in h1, out h2, residual h1 ----
    k_agg      <<<aggBlocks, 256>>>((const float*)0, 1, N);
    k_transpose<<<64, 256>>>(W2l, W2r);
    k_layer    <<<layerBlocks, 256>>>((const float*)0, 1, b2, 1, 2, N);

    // ---- layer 3: in h2, out h3, residual h2 ----
    k_agg      <<<aggBlocks, 256>>>((const float*)0, 2, N);
    k_transpose<<<64, 256>>>(W3l, W3r);
    k_layer    <<<layerBlocks, 256>>>((const float*)0, 2, b3, 2, 3, N);

    // ---- head ----
    k_out<<<aggBlocks, 256>>>(Wo, bo, out, N);
}

// round 5
// speedup vs baseline: 1.8095x; 1.8095x over previous
#include <cuda_runtime.h>
#include <math.h>
#include <stdint.h>

#define NMAX 100000
#define EMAX 1600000
#define HDIM 128

// ---------------- scratch (device globals; referenced by name only) --------
__device__ __align__(16) float g_m [NMAX * HDIM];
__device__ __align__(16) float g_h1[NMAX * HDIM];
__device__ __align__(16) float g_h2[NMAX * HDIM];
__device__ __align__(16) float g_h3[NMAX * HDIM];
__device__ int   g_deg[NMAX];
__device__ int   g_off[NMAX + 1];
__device__ int   g_cur[NMAX];
__device__ int   g_csr[EMAX];
__device__ int   g_bsum[128];
// tf32-converted transposed weights: 3 layers x [256 k][128 col]
__device__ __align__(16) uint32_t g_Wt[3 * 256 * 128];

__device__ __forceinline__ float* selbuf(int s) {
    switch (s) {
        case 1:  return g_h1;
        case 2:  return g_h2;
        case 3:  return g_h3;
        default: return g_m;
    }
}

__device__ __forceinline__ uint32_t f2tf32(float f) {
    uint32_t r;
    asm("cvt.rna.tf32.f32 %0, %1;" : "=r"(r) : "f"(f));
    return r;
}

#define MMA_TF32(d, a, b0v, b1v) \
    asm volatile( \
        "mma.sync.aligned.m16n8k8.row.col.f32.tf32.tf32.f32 " \
        "{%0,%1,%2,%3}, {%4,%5,%6,%7}, {%8,%9}, {%0,%1,%2,%3};" \
        : "+f"((d)[0]), "+f"((d)[1]), "+f"((d)[2]), "+f"((d)[3]) \
        : "r"((a)[0]), "r"((a)[1]), "r"((a)[2]), "r"((a)[3]), \
          "r"(b0v), "r"(b1v))

// ---------------- CSR build ------------------------------------------------
__global__ void k_zero(int n) {
    int i = blockIdx.x * blockDim.x + threadIdx.x;
    if (i < n) { g_deg[i] = 0; g_cur[i] = 0; }
}

__global__ void k_hist(const int* __restrict__ ei, int E, int n) {
    int e = blockIdx.x * blockDim.x + threadIdx.x;
    if (e < E) {
        int d = ei[E + e];
        if ((unsigned)d < (unsigned)n) atomicAdd(&g_deg[d], 1);
    }
}

__global__ void k_scan1(int n) {
    __shared__ int s[1024];
    int tid = threadIdx.x;
    int gid = blockIdx.x * 1024 + tid;
    int v = (gid < n) ? g_deg[gid] : 0;
    s[tid] = v;
    __syncthreads();
    for (int d = 1; d < 1024; d <<= 1) {
        int t = (tid >= d) ? s[tid - d] : 0;
        __syncthreads();
        s[tid] += t;
        __syncthreads();
    }
    if (gid < n) g_off[gid] = s[tid] - v;
    if (tid == 1023) g_bsum[blockIdx.x] = s[1023];
}

__global__ void k_scan2(int nb) {
    if (threadIdx.x == 0 && blockIdx.x == 0) {
        int acc = 0;
        for (int i = 0; i < nb; i++) { int t = g_bsum[i]; g_bsum[i] = acc; acc += t; }
    }
}

__global__ void k_scan3(int n, int E) {
    int gid = blockIdx.x * blockDim.x + threadIdx.x;
    if (gid < n)       g_off[gid] += g_bsum[gid >> 10];
    else if (gid == n) g_off[n] = E;
}

__global__ void k_fill(const int* __restrict__ ei, int E, int n) {
    int e = blockIdx.x * blockDim.x + threadIdx.x;
    if (e < E) {
        int s = ei[e];
        int d = ei[E + e];
        if ((unsigned)s < (unsigned)n && (unsigned)d < (unsigned)n) {
            int pos = g_off[d] + atomicAdd(&g_cur[d], 1);
            if ((unsigned)pos < (unsigned)E) g_csr[pos] = s;
        }
    }
}

// ---------------- per-node max aggregation (warp per node) -----------------
__global__ void k_agg(const float* __restrict__ hext, int hsel, int n) {
    const float* h = (hsel < 0) ? hext : selbuf(hsel);
    int w    = (blockIdx.x * blockDim.x + threadIdx.x) >> 5;
    int lane = threadIdx.x & 31;
    if (w >= n) return;
    int beg = g_off[w], end = g_off[w + 1];
    float4 mx = make_float4(0.f, 0.f, 0.f, 0.f);
    if (beg < end) {
        mx = make_float4(-INFINITY, -INFINITY, -INFINITY, -INFINITY);
        const float4* hv = (const float4*)h;
        int j = beg;
        for (; j + 1 < end; j += 2) {
            int s0 = g_csr[j], s1 = g_csr[j + 1];
            float4 v0 = hv[(long long)s0 * 32 + lane];
            float4 v1 = hv[(long long)s1 * 32 + lane];
            mx.x = fmaxf(mx.x, fmaxf(v0.x, v1.x));
            mx.y = fmaxf(mx.y, fmaxf(v0.y, v1.y));
            mx.z = fmaxf(mx.z, fmaxf(v0.z, v1.z));
            mx.w = fmaxf(mx.w, fmaxf(v0.w, v1.w));
        }
        if (j < end) {
            int s0 = g_csr[j];
            float4 v0 = hv[(long long)s0 * 32 + lane];
            mx.x = fmaxf(mx.x, v0.x);
            mx.y = fmaxf(mx.y, v0.y);
            mx.z = fmaxf(mx.z, v0.z);
            mx.w = fmaxf(mx.w, v0.w);
        }
    }
    ((float4*)g_m)[(long long)w * 32 + lane] = mx;
}

// ---------------- weight prep: tf32 bits of W^T (k-major) ------------------
// g_Wt[widx][k][j] = tf32( k<128 ? Wl[j][k] : Wr[j][k-128] )
__global__ void k_prepW(const float* __restrict__ Wl,
                        const float* __restrict__ Wr, int widx) {
    int idx = blockIdx.x * blockDim.x + threadIdx.x;
    if (idx >= 256 * 128) return;
    int k = idx >> 7, j = idx & 127;
    float v = (k < HDIM) ? Wl[j * HDIM + k] : Wr[j * HDIM + (k - HDIM)];
    g_Wt[widx * 32768 + k * 128 + j] = f2tf32(v);
}

// ---------------- mma.sync tf32 layer: GEMM + bias + ELU + residual --------
// out[i,:] = elu( [m|h][i,:] @ Wcat^T + b ) (+ res)
// block = 128 nodes x 128 cols, 8 warps (4 row-groups x 2 col-groups).
// K=256 in 8 chunks of 32. Fs [128][36] (A, tf32 bits), Ws [32][136] (B).
#define FS_ST 36
#define WS_ST 136

__global__ void __launch_bounds__(256) k_layer_mma(
    const float* __restrict__ hext, int hsel,
    const float* __restrict__ bias, int ressel, int outsel, int wsel, int n) {
    __shared__ __align__(16) uint32_t Fs[128 * FS_ST];
    __shared__ __align__(16) uint32_t Ws[32 * WS_ST];

    const float* h   = (hsel < 0)   ? hext : selbuf(hsel);
    const float* m   = g_m;
    const float* res = (ressel < 0) ? (const float*)0 : selbuf(ressel);
    float*       out = selbuf(outsel);
    const uint32_t* wt = g_Wt + wsel * 32768;

    const int tid  = threadIdx.x;
    const int wid  = tid >> 5;
    const int lane = tid & 31;
    const int gi   = lane >> 2;   // group id 0..7
    const int ti   = lane & 3;    // thread-in-group 0..3
    const int wr   = wid & 3;     // row group: rows wr*32..+31
    const int wc   = wid >> 2;    // col group: cols wc*64..+63
    const int base = blockIdx.x * 128;

    // staging assignments
    const int s_node = tid >> 1;            // 0..127
    const int s_kb   = (tid & 1) * 16;      // 0 or 16
    const int gn_row = base + s_node;

    float acc[2][8][4];
#pragma unroll
    for (int mt = 0; mt < 2; mt++)
#pragma unroll
        for (int nt = 0; nt < 8; nt++)
#pragma unroll
            for (int q = 0; q < 4; q++) acc[mt][nt][q] = 0.f;

    for (int kc = 0; kc < 8; kc++) {
        const float* src = (kc < 4) ? m : h;
        const int k0 = (kc & 3) * 32;
        __syncthreads();
        // B chunk: [32][128] contiguous -> [32][WS_ST] padded
        {
            const uint4* bs = (const uint4*)(wt + kc * 4096);
#pragma unroll
            for (int r = 0; r < 4; r++) {
                int lin4 = r * 256 + tid;          // 0..1023 float4s
                int k = lin4 >> 5, c4 = lin4 & 31;
                *(uint4*)&Ws[k * WS_ST + c4 * 4] = bs[lin4];
            }
        }
        // A chunk: fp32 global -> tf32 bits, [128][FS_ST]
#pragma unroll
        for (int v = 0; v < 4; v++) {
            int kk = s_kb + v * 4;
            float4 f = make_float4(0.f, 0.f, 0.f, 0.f);
            if (gn_row < n)
                f = *(const float4*)(src + (size_t)gn_row * HDIM + k0 + kk);
            uint4 t;
            t.x = f2tf32(f.x); t.y = f2tf32(f.y);
            t.z = f2tf32(f.z); t.w = f2tf32(f.w);
            *(uint4*)&Fs[s_node * FS_ST + kk] = t;
        }
        __syncthreads();

#pragma unroll
        for (int ks = 0; ks < 4; ks++) {
            const int kb = ks * 8;
            uint32_t a[2][4];
#pragma unroll
            for (int mt = 0; mt < 2; mt++) {
                int rb = wr * 32 + mt * 16;
                a[mt][0] = Fs[(rb + gi)     * FS_ST + kb + ti];
                a[mt][1] = Fs[(rb + 8 + gi) * FS_ST + kb + ti];
                a[mt][2] = Fs[(rb + gi)     * FS_ST + kb + ti + 4];
                a[mt][3] = Fs[(rb + 8 + gi) * FS_ST + kb + ti + 4];
            }
#pragma unroll
            for (int nt = 0; nt < 8; nt++) {
                int cb = wc * 64 + nt * 8 + gi;
                uint32_t b0 = Ws[(kb + ti)     * WS_ST + cb];
                uint32_t b1 = Ws[(kb + 4 + ti) * WS_ST + cb];
                MMA_TF32(acc[0][nt], a[0], b0, b1);
                MMA_TF32(acc[1][nt], a[1], b0, b1);
            }
        }
    }

    // epilogue: bias + ELU + residual + store (float2 per half-tile)
#pragma unroll
    for (int nt = 0; nt < 8; nt++) {
        int col = wc * 64 + nt * 8 + ti * 2;
        float bb0 = bias[col], bb1 = bias[col + 1];
#pragma unroll
        for (int mt = 0; mt < 2; mt++) {
#pragma unroll
            for (int half = 0; half < 2; half++) {
                int row = base + wr * 32 + mt * 16 + gi + half * 8;
                if (row >= n) continue;
                float v0 = acc[mt][nt][half * 2 + 0] + bb0;
                float v1 = acc[mt][nt][half * 2 + 1] + bb1;
                v0 = (v0 > 0.f) ? v0 : expm1f(v0);
                v1 = (v1 > 0.f) ? v1 : expm1f(v1);
                size_t o = (size_t)row * HDIM + col;
                if (res) {
                    float2 rr = *(const float2*)(res + o);
                    v0 += rr.x; v1 += rr.y;
                }
                *(float2*)(out + o) = make_float2(v0, v1);
            }
        }
    }
}

// ---------------- output head: sigmoid(h3 @ Wo^T + bo) ---------------------
__global__ void k_out(const float* __restrict__ Wo, const float* __restrict__ bo,
                      float* __restrict__ out, int n) {
    const float* h = g_h3;
    int w    = (blockIdx.x * blockDim.x + threadIdx.x) >> 5;
    int lane = threadIdx.x & 31;
    if (w >= n) return;
    float4 v  = ((const float4*)h)[(long long)w * 32 + lane];
    float4 wo = ((const float4*)Wo)[lane];
    float d = v.x * wo.x + v.y * wo.y + v.z * wo.z + v.w * wo.w;
#pragma unroll
    for (int o = 16; o > 0; o >>= 1) d += __shfl_xor_sync(0xffffffff, d, o);
    if (lane == 0) {
        float z = d + bo[0];
        out[w] = 1.f / (1.f + expf(-z));
    }
}

// ---------------- launcher (kernel launches ONLY) ---------------------------
extern "C" void kernel_launch(void* const* d_in, const int* in_sizes, int n_in,
                              void* d_out, int out_size) {
    const float* x   = (const float*)d_in[0];
    const int*   ei  = (const int*)d_in[1];     // edge_index is int32
    const float* W1l = (const float*)d_in[2];
    const float* b1  = (const float*)d_in[3];
    const float* W1r = (const float*)d_in[4];
    const float* W2l = (const float*)d_in[5];
    const float* b2  = (const float*)d_in[6];
    const float* W2r = (const float*)d_in[7];
    const float* W3l = (const float*)d_in[8];
    const float* b3  = (const float*)d_in[9];
    const float* W3r = (const float*)d_in[10];
    const float* Wo  = (const float*)d_in[11];
    const float* bo  = (const float*)d_in[12];
    float* out = (float*)d_out;

    int N = in_sizes[0] / HDIM;
    int E = in_sizes[1] / 2;
    if (N > NMAX) N = NMAX;
    if (E > EMAX) E = EMAX;

    // ---- CSR build (dst-sorted adjacency) ----
    k_zero <<<(N + 255) / 256, 256>>>(N);
    k_hist <<<(E + 255) / 256, 256>>>(ei, E, N);
    int nb = (N + 1023) / 1024;
    k_scan1<<<nb, 1024>>>(N);
    k_scan2<<<1, 32>>>(nb);
    k_scan3<<<(N + 1 + 1023) / 1024, 1024>>>(N, E);
    k_fill <<<(E + 255) / 256, 256>>>(ei, E, N);

    // ---- weight prep ----
    k_prepW<<<128, 256>>>(W1l, W1r, 0);
    k_prepW<<<128, 256>>>(W2l, W2r, 1);
    k_prepW<<<128, 256>>>(W3l, W3r, 2);

    int aggBlocks   = (N * 32 + 255) / 256;
    int layerBlocks = (N + 127) / 128;

    // ---- layer 1: in x, out h1, no residual ----
    k_agg      <<<aggBlocks, 256>>>(x, -1, N);
    k_layer_mma<<<layerBlocks, 256>>>(x, -1, b1, -1, 1, 0, N);

    // ---- layer 2: in h1, out h2, residual h1 ----
    k_agg      <<<aggBlocks, 256>>>((const float*)0, 1, N);
    k_layer_mma<<<layerBlocks, 256>>>((const float*)0, 1, b2, 1, 2, 1, N);

    // ---- layer 3: in h2, out h3, residual h2 ----
    k_agg      <<<aggBlocks, 256>>>((const float*)0, 2, N);
    k_layer_mma<<<layerBlocks, 256>>>((const float*)0, 2, b3, 2, 3, 2, N);

    // ---- head ----
    k_out<<<aggBlocks, 256>>>(Wo, bo, out, N);
}

// round 6
// speedup vs baseline: 2.0844x; 1.1519x over previous
#include <cuda_runtime.h>
#include <cuda_fp16.h>
#include <math.h>
#include <stdint.h>

#define NMAX 100000
#define EMAX 1600000
#define HDIM 128

// ---------------- scratch (device globals; referenced by name only) --------
__device__ __align__(16) __half g_m [NMAX * HDIM];   // aggregated max (fp16, lossless)
__device__ __align__(16) __half g_fh[NMAX * HDIM];   // fp16 mirror of current layer input
__device__ __align__(16) float g_h1[NMAX * HDIM];
__device__ __align__(16) float g_h2[NMAX * HDIM];
__device__ __align__(16) float g_h3[NMAX * HDIM];
__device__ int   g_deg[NMAX];
__device__ int   g_off[NMAX + 1];
__device__ int   g_cur[NMAX];
__device__ int   g_csr[EMAX];
__device__ int   g_bsum[128];
// tf32-converted transposed weights: 3 layers x [256 k][128 col]
__device__ __align__(16) uint32_t g_Wt[3 * 256 * 128];

__device__ __forceinline__ float* selbuf(int s) {
    switch (s) {
        case 1:  return g_h1;
        case 2:  return g_h2;
        default: return g_h3;
    }
}

__device__ __forceinline__ uint32_t f2tf32(float f) {
    uint32_t r;
    asm("cvt.rna.tf32.f32 %0, %1;" : "=r"(r) : "f"(f));
    return r;
}

#define MMA_TF32(d, a, b0v, b1v) \
    asm volatile( \
        "mma.sync.aligned.m16n8k8.row.col.f32.tf32.tf32.f32 " \
        "{%0,%1,%2,%3}, {%4,%5,%6,%7}, {%8,%9}, {%0,%1,%2,%3};" \
        : "+f"((d)[0]), "+f"((d)[1]), "+f"((d)[2]), "+f"((d)[3]) \
        : "r"((a)[0]), "r"((a)[1]), "r"((a)[2]), "r"((a)[3]), \
          "r"(b0v), "r"(b1v))

// ---------------- CSR build ------------------------------------------------
__global__ void k_zero(int n) {
    int i = blockIdx.x * blockDim.x + threadIdx.x;
    if (i < n) { g_deg[i] = 0; g_cur[i] = 0; }
}

__global__ void k_hist(const int* __restrict__ ei, int E, int n) {
    int e = blockIdx.x * blockDim.x + threadIdx.x;
    if (e < E) {
        int d = ei[E + e];
        if ((unsigned)d < (unsigned)n) atomicAdd(&g_deg[d], 1);
    }
}

__global__ void k_scan1(int n) {
    __shared__ int s[1024];
    int tid = threadIdx.x;
    int gid = blockIdx.x * 1024 + tid;
    int v = (gid < n) ? g_deg[gid] : 0;
    s[tid] = v;
    __syncthreads();
    for (int d = 1; d < 1024; d <<= 1) {
        int t = (tid >= d) ? s[tid - d] : 0;
        __syncthreads();
        s[tid] += t;
        __syncthreads();
    }
    if (gid < n) g_off[gid] = s[tid] - v;
    if (tid == 1023) g_bsum[blockIdx.x] = s[1023];
}

__global__ void k_scan2(int nb) {
    __shared__ int s[128];
    int tid = threadIdx.x;
    int v = (tid < nb) ? g_bsum[tid] : 0;
    s[tid] = v;
    __syncthreads();
    for (int d = 1; d < 128; d <<= 1) {
        int t = (tid >= d) ? s[tid - d] : 0;
        __syncthreads();
        s[tid] += t;
        __syncthreads();
    }
    if (tid < nb) g_bsum[tid] = s[tid] - v;   // exclusive
}

__global__ void k_scan3(int n, int E) {
    int gid = blockIdx.x * blockDim.x + threadIdx.x;
    if (gid < n)       g_off[gid] += g_bsum[gid >> 10];
    else if (gid == n) g_off[n] = E;
}

__global__ void k_fill(const int* __restrict__ ei, int E, int n) {
    int e = blockIdx.x * blockDim.x + threadIdx.x;
    if (e < E) {
        int s = ei[e];
        int d = ei[E + e];
        if ((unsigned)s < (unsigned)n && (unsigned)d < (unsigned)n) {
            int pos = g_off[d] + atomicAdd(&g_cur[d], 1);
            if ((unsigned)pos < (unsigned)E) g_csr[pos] = s;
        }
    }
}

// ---------------- x -> fp16 mirror ------------------------------------------
__global__ void k_conv(const float* __restrict__ x, int total4) {
    int i = blockIdx.x * blockDim.x + threadIdx.x;
    if (i >= total4) return;
    float4 f = ((const float4*)x)[i];
    __half2 h0 = __floats2half2_rn(f.x, f.y);
    __half2 h1 = __floats2half2_rn(f.z, f.w);
    uint2 u;
    u.x = *(uint32_t*)&h0;
    u.y = *(uint32_t*)&h1;
    ((uint2*)g_fh)[i] = u;
}

// ---------------- per-node max aggregation (warp per node, fp16) ------------
// reads g_fh; writes g_m (fp16). lane covers 4 halves (8B) of the 256B row.
__global__ void k_agg(int n) {
    int w    = (blockIdx.x * blockDim.x + threadIdx.x) >> 5;
    int lane = threadIdx.x & 31;
    if (w >= n) return;
    int beg = g_off[w], end = g_off[w + 1];
    uint2 outv;
    if (beg < end) {
        const uint2* hv = (const uint2*)g_fh;   // row stride 32 uint2
        const uint32_t NEG = 0xFBFFFBFFu;        // half2(-65504,-65504)
        __half2 a0 = *(const __half2*)&NEG;
        __half2 a1 = a0;
        int j = beg;
        for (; j + 1 < end; j += 2) {
            int s0 = g_csr[j], s1 = g_csr[j + 1];
            uint2 v0 = hv[(size_t)s0 * 32 + lane];
            uint2 v1 = hv[(size_t)s1 * 32 + lane];
            a0 = __hmax2(a0, __hmax2(*(__half2*)&v0.x, *(__half2*)&v1.x));
            a1 = __hmax2(a1, __hmax2(*(__half2*)&v0.y, *(__half2*)&v1.y));
        }
        if (j < end) {
            uint2 v0 = hv[(size_t)g_csr[j] * 32 + lane];
            a0 = __hmax2(a0, *(__half2*)&v0.x);
            a1 = __hmax2(a1, *(__half2*)&v0.y);
        }
        outv.x = *(uint32_t*)&a0;
        outv.y = *(uint32_t*)&a1;
    } else {
        outv.x = 0; outv.y = 0;   // empty segment -> 0 (PyG semantics)
    }
    ((uint2*)g_m)[(size_t)w * 32 + lane] = outv;
}

// ---------------- weight prep: tf32 bits of W^T (k-major), all 3 layers ----
__global__ void k_prepW(const float* __restrict__ W1l, const float* __restrict__ W1r,
                        const float* __restrict__ W2l, const float* __restrict__ W2r,
                        const float* __restrict__ W3l, const float* __restrict__ W3r) {
    int idx = blockIdx.x * blockDim.x + threadIdx.x;
    if (idx >= 3 * 256 * 128) return;
    int widx = idx >> 15;
    int rem  = idx & 32767;
    int k = rem >> 7, j = rem & 127;
    const float* Wl = (widx == 0) ? W1l : (widx == 1) ? W2l : W3l;
    const float* Wr = (widx == 0) ? W1r : (widx == 1) ? W2r : W3r;
    float v = (k < HDIM) ? Wl[j * HDIM + k] : Wr[j * HDIM + (k - HDIM)];
    g_Wt[idx] = f2tf32(v);
}

// ---------------- mma.sync tf32 layer: GEMM + bias + ELU + residual --------
// out[i,:] = elu( [m|fh][i,:] @ Wcat^T + b ) (+ res);  fp16 mirror optionally updated
#define FS_ST 36
#define WS_ST 136

__device__ __forceinline__ uint2 h2tf(uint32_t h) {
    float2 f = __half22float2(*(__half2*)&h);
    uint2 r;
    r.x = __float_as_uint(f.x);
    r.y = __float_as_uint(f.y);
    return r;   // fp16-derived floats are exact tf32 values
}

__global__ void __launch_bounds__(256) k_layer_mma(
    const float* __restrict__ bias, int ressel, int outsel, int wsel,
    int wrfh, int n) {
    __shared__ __align__(16) uint32_t Fs[128 * FS_ST];
    __shared__ __align__(16) uint32_t Ws[32 * WS_ST];

    const float* res = (ressel < 0) ? (const float*)0 : selbuf(ressel);
    float*       out = selbuf(outsel);
    const uint32_t* wt = g_Wt + wsel * 32768;

    const int tid  = threadIdx.x;
    const int wid  = tid >> 5;
    const int lane = tid & 31;
    const int gi   = lane >> 2;
    const int ti   = lane & 3;
    const int wr   = wid & 3;
    const int wc   = wid >> 2;
    const int base = blockIdx.x * 128;

    const int s_node = tid >> 1;
    const int s_kb   = (tid & 1) * 16;
    const int gn_row = base + s_node;

    float acc[2][8][4];
#pragma unroll
    for (int mt = 0; mt < 2; mt++)
#pragma unroll
        for (int nt = 0; nt < 8; nt++)
#pragma unroll
            for (int q = 0; q < 4; q++) acc[mt][nt][q] = 0.f;

    for (int kc = 0; kc < 8; kc++) {
        const __half* srcH = (kc < 4) ? g_m : g_fh;
        const int k0 = (kc & 3) * 32;
        __syncthreads();
        // B chunk: [32][128] contiguous -> [32][WS_ST] padded
        {
            const uint4* bs = (const uint4*)(wt + kc * 4096);
#pragma unroll
            for (int r = 0; r < 4; r++) {
                int lin4 = r * 256 + tid;
                int k = lin4 >> 5, c4 = lin4 & 31;
                *(uint4*)&Ws[k * WS_ST + c4 * 4] = bs[lin4];
            }
        }
        // A chunk: fp16 global -> fp32 bits (tf32-exact), [128][FS_ST]
        {
            uint4 p0 = make_uint4(0, 0, 0, 0), p1 = p0;
            if (gn_row < n) {
                const __half* rp = srcH + (size_t)gn_row * HDIM + k0 + s_kb;
                p0 = *(const uint4*)rp;
                p1 = *(const uint4*)(rp + 8);
            }
            uint32_t* fd = &Fs[s_node * FS_ST + s_kb];
            uint2 c;
            c = h2tf(p0.x); fd[0]  = c.x; fd[1]  = c.y;
            c = h2tf(p0.y); fd[2]  = c.x; fd[3]  = c.y;
            c = h2tf(p0.z); fd[4]  = c.x; fd[5]  = c.y;
            c = h2tf(p0.w); fd[6]  = c.x; fd[7]  = c.y;
            c = h2tf(p1.x); fd[8]  = c.x; fd[9]  = c.y;
            c = h2tf(p1.y); fd[10] = c.x; fd[11] = c.y;
            c = h2tf(p1.z); fd[12] = c.x; fd[13] = c.y;
            c = h2tf(p1.w); fd[14] = c.x; fd[15] = c.y;
        }
        __syncthreads();

#pragma unroll
        for (int ks = 0; ks < 4; ks++) {
            const int kb = ks * 8;
            uint32_t a[2][4];
#pragma unroll
            for (int mt = 0; mt < 2; mt++) {
                int rb = wr * 32 + mt * 16;
                a[mt][0] = Fs[(rb + gi)     * FS_ST + kb + ti];
                a[mt][1] = Fs[(rb + 8 + gi) * FS_ST + kb + ti];
                a[mt][2] = Fs[(rb + gi)     * FS_ST + kb + ti + 4];
                a[mt][3] = Fs[(rb + 8 + gi) * FS_ST + kb + ti + 4];
            }
#pragma unroll
            for (int nt = 0; nt < 8; nt++) {
                int cb = wc * 64 + nt * 8 + gi;
                uint32_t b0 = Ws[(kb + ti)     * WS_ST + cb];
                uint32_t b1 = Ws[(kb + 4 + ti) * WS_ST + cb];
                MMA_TF32(acc[0][nt], a[0], b0, b1);
                MMA_TF32(acc[1][nt], a[1], b0, b1);
            }
        }
    }

    // epilogue: bias + ELU + residual + fp32 store + fp16 mirror
#pragma unroll
    for (int nt = 0; nt < 8; nt++) {
        int col = wc * 64 + nt * 8 + ti * 2;
        float bb0 = bias[col], bb1 = bias[col + 1];
#pragma unroll
        for (int mt = 0; mt < 2; mt++) {
#pragma unroll
            for (int half = 0; half < 2; half++) {
                int row = base + wr * 32 + mt * 16 + gi + half * 8;
                if (row >= n) continue;
                float v0 = acc[mt][nt][half * 2 + 0] + bb0;
                float v1 = acc[mt][nt][half * 2 + 1] + bb1;
                v0 = (v0 > 0.f) ? v0 : expm1f(v0);
                v1 = (v1 > 0.f) ? v1 : expm1f(v1);
                size_t o = (size_t)row * HDIM + col;
                if (res) {
                    float2 rr = *(const float2*)(res + o);
                    v0 += rr.x; v1 += rr.y;
                }
                *(float2*)(out + o) = make_float2(v0, v1);
                if (wrfh) {
                    __half2 hv = __floats2half2_rn(v0, v1);
                    *(__half2*)(g_fh + o) = hv;
                }
            }
        }
    }
}

// ---------------- output head: sigmoid(h3 @ Wo^T + bo) ---------------------
__global__ void k_out(const float* __restrict__ Wo, const float* __restrict__ bo,
                      float* __restrict__ out, int n) {
    const float* h = g_h3;
    int w    = (blockIdx.x * blockDim.x + threadIdx.x) >> 5;
    int lane = threadIdx.x & 31;
    if (w >= n) return;
    float4 v  = ((const float4*)h)[(size_t)w * 32 + lane];
    float4 wo = ((const float4*)Wo)[lane];
    float d = v.x * wo.x + v.y * wo.y + v.z * wo.z + v.w * wo.w;
#pragma unroll
    for (int o = 16; o > 0; o >>= 1) d += __shfl_xor_sync(0xffffffff, d, o);
    if (lane == 0) {
        float z = d + bo[0];
        out[w] = 1.f / (1.f + expf(-z));
    }
}

// ---------------- launcher (kernel launches ONLY) ---------------------------
extern "C" void kernel_launch(void* const* d_in, const int* in_sizes, int n_in,
                              void* d_out, int out_size) {
    const float* x   = (const float*)d_in[0];
    const int*   ei  = (const int*)d_in[1];     // edge_index is int32
    const float* W1l = (const float*)d_in[2];
    const float* b1  = (const float*)d_in[3];
    const float* W1r = (const float*)d_in[4];
    const float* W2l = (const float*)d_in[5];
    const float* b2  = (const float*)d_in[6];
    const float* W2r = (const float*)d_in[7];
    const float* W3l = (const float*)d_in[8];
    const float* b3  = (const float*)d_in[9];
    const float* W3r = (const float*)d_in[10];
    const float* Wo  = (const float*)d_in[11];
    const float* bo  = (const float*)d_in[12];
    float* out = (float*)d_out;

    int N = in_sizes[0] / HDIM;
    int E = in_sizes[1] / 2;
    if (N > NMAX) N = NMAX;
    if (E > EMAX) E = EMAX;

    // ---- CSR build (dst-sorted adjacency) ----
    k_zero <<<(N + 255) / 256, 256>>>(N);
    k_hist <<<(E + 255) / 256, 256>>>(ei, E, N);
    int nb = (N + 1023) / 1024;
    k_scan1<<<nb, 1024>>>(N);
    k_scan2<<<1, 128>>>(nb);
    k_scan3<<<(N + 1 + 1023) / 1024, 1024>>>(N, E);
    k_fill <<<(E + 255) / 256, 256>>>(ei, E, N);

    // ---- weight prep + x fp16 mirror ----
    k_prepW<<<384, 256>>>(W1l, W1r, W2l, W2r, W3l, W3r);
    int total4 = N * HDIM / 4;
    k_conv<<<(total4 + 255) / 256, 256>>>(x, total4);

    int aggBlocks   = (N * 32 + 255) / 256;
    int layerBlocks = (N + 127) / 128;

    // ---- layer 1: agg(fp16 x) -> GEMM -> h1 fp32 + fp16 mirror ----
    k_agg      <<<aggBlocks, 256>>>(N);
    k_layer_mma<<<layerBlocks, 256>>>(b1, -1, 1, 0, 1, N);

    // ---- layer 2: residual h1 ----
    k_agg      <<<aggBlocks, 256>>>(N);
    k_layer_mma<<<layerBlocks, 256>>>(b2, 1, 2, 1, 1, N);

    // ---- layer 3: residual h2 (no mirror needed) ----
    k_agg      <<<aggBlocks, 256>>>(N);
    k_layer_mma<<<layerBlocks, 256>>>(b3, 2, 3, 2, 0, N);

    // ---- head ----
    k_out<<<aggBlocks, 256>>>(Wo, bo, out, N);
}

// round 7
// speedup vs baseline: 2.4052x; 1.1539x over previous
#include <cuda_runtime.h>
#include <cuda_fp16.h>
#include <math.h>
#include <stdint.h>

#define NMAX 100000
#define EMAX 1600000
#define HDIM 128

// ---------------- scratch (device globals; referenced by name only) --------
__device__ __align__(16) __half g_m [NMAX * HDIM];   // aggregated max (fp16)
__device__ __align__(16) __half g_fh[NMAX * HDIM];   // fp16 mirror of layer input
__device__ __align__(16) float g_h1[NMAX * HDIM];
__device__ __align__(16) float g_h2[NMAX * HDIM];
__device__ int   g_deg[NMAX];
__device__ int   g_off[NMAX + 1];
__device__ int   g_cur[NMAX];
__device__ int   g_csr[EMAX];
__device__ int   g_bsum[128];
// fp16 weights in mma-ready layout: [3][8 kc][128 col][16 half2]
__device__ __align__(16) uint32_t g_Wh[3 * 8 * 128 * 16];

__device__ __forceinline__ float* selbuf(int s) {
    return (s == 1) ? g_h1 : g_h2;
}

#define MMA_F16(d, a, b0v, b1v) \
    asm volatile( \
        "mma.sync.aligned.m16n8k16.row.col.f32.f16.f16.f32 " \
        "{%0,%1,%2,%3}, {%4,%5,%6,%7}, {%8,%9}, {%0,%1,%2,%3};" \
        : "+f"((d)[0]), "+f"((d)[1]), "+f"((d)[2]), "+f"((d)[3]) \
        : "r"((a)[0]), "r"((a)[1]), "r"((a)[2]), "r"((a)[3]), \
          "r"(b0v), "r"(b1v))

// ---------------- CSR build ------------------------------------------------
__global__ void k_zero(int n) {
    int i = blockIdx.x * blockDim.x + threadIdx.x;
    if (i < n) g_deg[i] = 0;
}

__global__ void k_hist(const int* __restrict__ ei, int E, int n) {
    int e = blockIdx.x * blockDim.x + threadIdx.x;
    if (e < E) {
        int d = ei[E + e];
        if ((unsigned)d < (unsigned)n) atomicAdd(&g_deg[d], 1);
    }
}

__global__ void k_scan1(int n) {
    __shared__ int s[1024];
    int tid = threadIdx.x;
    int gid = blockIdx.x * 1024 + tid;
    int v = (gid < n) ? g_deg[gid] : 0;
    s[tid] = v;
    __syncthreads();
    for (int d = 1; d < 1024; d <<= 1) {
        int t = (tid >= d) ? s[tid - d] : 0;
        __syncthreads();
        s[tid] += t;
        __syncthreads();
    }
    if (gid < n) g_off[gid] = s[tid] - v;
    if (tid == 1023) g_bsum[blockIdx.x] = s[1023];
}

__global__ void k_scan2(int nb) {
    __shared__ int s[128];
    int tid = threadIdx.x;
    int v = (tid < nb) ? g_bsum[tid] : 0;
    s[tid] = v;
    __syncthreads();
    for (int d = 1; d < 128; d <<= 1) {
        int t = (tid >= d) ? s[tid - d] : 0;
        __syncthreads();
        s[tid] += t;
        __syncthreads();
    }
    if (tid < nb) g_bsum[tid] = s[tid] - v;   // exclusive
}

__global__ void k_scan3(int n, int E) {
    int gid = blockIdx.x * blockDim.x + threadIdx.x;
    if (gid < n) {
        int o = g_off[gid] + g_bsum[gid >> 10];
        g_off[gid] = o;
        g_cur[gid] = o;          // running cursor for k_fill
    } else if (gid == n) {
        g_off[n] = E;
    }
}

__global__ void k_fill(const int* __restrict__ ei, int E, int n) {
    int e = blockIdx.x * blockDim.x + threadIdx.x;
    if (e < E) {
        int s = ei[e];
        int d = ei[E + e];
        if ((unsigned)s < (unsigned)n && (unsigned)d < (unsigned)n) {
            int pos = atomicAdd(&g_cur[d], 1);
            if ((unsigned)pos < (unsigned)E) g_csr[pos] = s;
        }
    }
}

// ---------------- x -> fp16 mirror ------------------------------------------
__global__ void k_conv(const float* __restrict__ x, int total4) {
    int i = blockIdx.x * blockDim.x + threadIdx.x;
    if (i >= total4) return;
    float4 f = ((const float4*)x)[i];
    __half2 h0 = __floats2half2_rn(f.x, f.y);
    __half2 h1 = __floats2half2_rn(f.z, f.w);
    uint2 u;
    u.x = *(uint32_t*)&h0;
    u.y = *(uint32_t*)&h1;
    ((uint2*)g_fh)[i] = u;
}

// ---------------- per-node max aggregation (warp per node, fp16) ------------
__global__ void k_agg(int n) {
    int w    = (blockIdx.x * blockDim.x + threadIdx.x) >> 5;
    int lane = threadIdx.x & 31;
    if (w >= n) return;
    int beg = g_off[w], end = g_off[w + 1];
    uint2 outv;
    if (beg < end) {
        const uint2* hv = (const uint2*)g_fh;
        const uint32_t NEG = 0xFBFFFBFFu;        // half2(-65504,-65504)
        __half2 a0 = *(const __half2*)&NEG;
        __half2 a1 = a0;
        int j = beg;
        for (; j + 1 < end; j += 2) {
            int s0 = g_csr[j], s1 = g_csr[j + 1];
            uint2 v0 = hv[(size_t)s0 * 32 + lane];
            uint2 v1 = hv[(size_t)s1 * 32 + lane];
            a0 = __hmax2(a0, __hmax2(*(__half2*)&v0.x, *(__half2*)&v1.x));
            a1 = __hmax2(a1, __hmax2(*(__half2*)&v0.y, *(__half2*)&v1.y));
        }
        if (j < end) {
            uint2 v0 = hv[(size_t)g_csr[j] * 32 + lane];
            a0 = __hmax2(a0, *(__half2*)&v0.x);
            a1 = __hmax2(a1, *(__half2*)&v0.y);
        }
        outv.x = *(uint32_t*)&a0;
        outv.y = *(uint32_t*)&a1;
    } else {
        outv.x = 0; outv.y = 0;   // empty segment -> 0 (PyG semantics)
    }
    ((uint2*)g_m)[(size_t)w * 32 + lane] = outv;
}

// ---------------- weight prep: fp16 W^T in mma B layout ---------------------
// g_Wh[widx][kc][col][hp] = half2( W(col, kc*32+2hp), W(col, kc*32+2hp+1) )
// W(col,k) = k<128 ? Wl[col][k] : Wr[col][k-128]
__global__ void k_prepW(const float* __restrict__ W1l, const float* __restrict__ W1r,
                        const float* __restrict__ W2l, const float* __restrict__ W2r,
                        const float* __restrict__ W3l, const float* __restrict__ W3r) {
    int idx = blockIdx.x * blockDim.x + threadIdx.x;
    if (idx >= 3 * 8 * 128 * 16) return;
    int widx = idx >> 14;
    int rem  = idx & 16383;
    int kc   = rem >> 11;
    int rem2 = rem & 2047;
    int col  = rem2 >> 4;
    int hp   = rem2 & 15;
    int k    = kc * 32 + hp * 2;
    const float* Wl = (widx == 0) ? W1l : (widx == 1) ? W2l : W3l;
    const float* Wr = (widx == 0) ? W1r : (widx == 1) ? W2r : W3r;
    float v0 = (k < HDIM)     ? Wl[col * HDIM + k]       : Wr[col * HDIM + k - HDIM];
    float v1 = (k + 1 < HDIM) ? Wl[col * HDIM + k + 1]   : Wr[col * HDIM + k + 1 - HDIM];
    __half2 h = __floats2half2_rn(v0, v1);
    g_Wh[idx] = *(uint32_t*)&h;
}

// ---------------- fp16 mma layer: GEMM + bias + ELU + residual (+head) -----
// out[i,:] = elu( [m|fh][i,:] @ Wcat^T + b ) (+ res)
// fuse=1: instead of storing, compute sigmoid(h3 . Wo + bo) -> outv
#define FS_ST 20   // uint32 stride (16 data + 4 pad): conflict-free (gcd trick)
#define WS_ST 20

__global__ void __launch_bounds__(256) k_layer_mma(
    const float* __restrict__ bias, int ressel, int outsel, int wsel,
    int wrfh, int fuse,
    const float* __restrict__ Wo, const float* __restrict__ bo,
    float* __restrict__ outv, int n) {
    __shared__ __align__(16) uint32_t Fs[128 * FS_ST];
    __shared__ __align__(16) uint32_t Ws[128 * WS_ST];
    __shared__ float sPart[128 * 2];

    const float* res = (ressel < 0) ? (const float*)0 : selbuf(ressel);
    float*       out = selbuf(outsel);
    const uint32_t* wh = g_Wh + wsel * 16384;

    const int tid  = threadIdx.x;
    const int wid  = tid >> 5;
    const int lane = tid & 31;
    const int gi   = lane >> 2;
    const int ti   = lane & 3;
    const int wr   = wid & 3;     // rows wr*32..+31
    const int wc   = wid >> 2;    // cols wc*64..+63
    const int base = blockIdx.x * 128;

    const int s_node = tid >> 1;
    const int s_half = tid & 1;            // 16-half segment
    const int gn_row = base + s_node;

    float acc[2][8][4];
#pragma unroll
    for (int mt = 0; mt < 2; mt++)
#pragma unroll
        for (int nt = 0; nt < 8; nt++)
#pragma unroll
            for (int q = 0; q < 4; q++) acc[mt][nt][q] = 0.f;

    for (int kc = 0; kc < 8; kc++) {
        const __half* srcH = (kc < 4) ? g_m : g_fh;
        const int k0 = (kc & 3) * 32;
        __syncthreads();
        // B chunk: [128 col][16 half2] -> Ws stride 20
        {
            const uint4* bs = (const uint4*)(wh + kc * 2048);
#pragma unroll
            for (int r = 0; r < 2; r++) {
                int lin4 = r * 256 + tid;          // 0..511
                int col = lin4 >> 2, c4 = lin4 & 3;
                *(uint4*)&Ws[col * WS_ST + c4 * 4] = bs[lin4];
            }
        }
        // A chunk: fp16 rows, [128 node][16 half2] -> Fs stride 20
        {
            uint4 p0 = make_uint4(0, 0, 0, 0), p1 = p0;
            if (gn_row < n) {
                const __half* rp = srcH + (size_t)gn_row * HDIM + k0 + s_half * 16;
                p0 = *(const uint4*)rp;
                p1 = *(const uint4*)(rp + 8);
            }
            uint32_t* fd = &Fs[s_node * FS_ST + s_half * 8];
            *(uint4*)fd       = p0;
            *(uint4*)(fd + 4) = p1;
        }
        __syncthreads();

#pragma unroll
        for (int ks = 0; ks < 2; ks++) {
            const int kb = ks * 8;                 // half2 offset
            uint32_t a[2][4];
#pragma unroll
            for (int mt = 0; mt < 2; mt++) {
                int rb = wr * 32 + mt * 16;
                a[mt][0] = Fs[(rb + gi)     * FS_ST + kb + ti];
                a[mt][1] = Fs[(rb + 8 + gi) * FS_ST + kb + ti];
                a[mt][2] = Fs[(rb + gi)     * FS_ST + kb + ti + 4];
                a[mt][3] = Fs[(rb + 8 + gi) * FS_ST + kb + ti + 4];
            }
#pragma unroll
            for (int nt = 0; nt < 8; nt++) {
                int cb = wc * 64 + nt * 8 + gi;
                uint32_t b0 = Ws[cb * WS_ST + kb + ti];
                uint32_t b1 = Ws[cb * WS_ST + kb + ti + 4];
                MMA_F16(acc[0][nt], a[0], b0, b1);
                MMA_F16(acc[1][nt], a[1], b0, b1);
            }
        }
    }

    // ---------------- epilogue ----------------
    float part[2][2] = {{0.f, 0.f}, {0.f, 0.f}};   // [mt][half] head partials
#pragma unroll
    for (int nt = 0; nt < 8; nt++) {
        int col = wc * 64 + nt * 8 + ti * 2;
        float bb0 = bias[col], bb1 = bias[col + 1];
        float wo0 = 0.f, wo1 = 0.f;
        if (fuse) { wo0 = Wo[col]; wo1 = Wo[col + 1]; }
#pragma unroll
        for (int mt = 0; mt < 2; mt++) {
#pragma unroll
            for (int half = 0; half < 2; half++) {
                int row = base + wr * 32 + mt * 16 + gi + half * 8;
                if (row >= n) continue;
                float v0 = acc[mt][nt][half * 2 + 0] + bb0;
                float v1 = acc[mt][nt][half * 2 + 1] + bb1;
                v0 = (v0 > 0.f) ? v0 : expm1f(v0);
                v1 = (v1 > 0.f) ? v1 : expm1f(v1);
                size_t o = (size_t)row * HDIM + col;
                if (res) {
                    float2 rr = *(const float2*)(res + o);
                    v0 += rr.x; v1 += rr.y;
                }
                if (fuse) {
                    part[mt][half] += v0 * wo0 + v1 * wo1;
                } else {
                    *(float2*)(out + o) = make_float2(v0, v1);
                    if (wrfh) {
                        __half2 hv = __floats2half2_rn(v0, v1);
                        *(__half2*)(g_fh + o) = hv;
                    }
                }
            }
        }
    }

    if (fuse) {
        // reduce head partials: over ti (shfl), then over wc (smem)
#pragma unroll
        for (int mt = 0; mt < 2; mt++)
#pragma unroll
            for (int half = 0; half < 2; half++) {
                float p = part[mt][half];
                p += __shfl_xor_sync(0xffffffff, p, 1);
                p += __shfl_xor_sync(0xffffffff, p, 2);
                if (ti == 0) {
                    int rl = wr * 32 + mt * 16 + gi + half * 8;
                    sPart[rl * 2 + wc] = p;
                }
            }
        __syncthreads();
        if (tid < 128) {
            int row = base + tid;
            if (row < n) {
                float z = sPart[tid * 2] + sPart[tid * 2 + 1] + bo[0];
                outv[row] = 1.f / (1.f + expf(-z));
            }
        }
    }
}

// ---------------- launcher (kernel launches ONLY) ---------------------------
extern "C" void kernel_launch(void* const* d_in, const int* in_sizes, int n_in,
                              void* d_out, int out_size) {
    const float* x   = (const float*)d_in[0];
    const int*   ei  = (const int*)d_in[1];     // edge_index is int32
    const float* W1l = (const float*)d_in[2];
    const float* b1  = (const float*)d_in[3];
    const float* W1r = (const float*)d_in[4];
    const float* W2l = (const float*)d_in[5];
    const float* b2  = (const float*)d_in[6];
    const float* W2r = (const float*)d_in[7];
    const float* W3l = (const float*)d_in[8];
    const float* b3  = (const float*)d_in[9];
    const float* W3r = (const float*)d_in[10];
    const float* Wo  = (const float*)d_in[11];
    const float* bo  = (const float*)d_in[12];
    float* out = (float*)d_out;

    int N = in_sizes[0] / HDIM;
    int E = in_sizes[1] / 2;
    if (N > NMAX) N = NMAX;
    if (E > EMAX) E = EMAX;

    // ---- CSR build (dst-sorted adjacency) ----
    k_zero <<<(N + 255) / 256, 256>>>(N);
    k_hist <<<(E + 255) / 256, 256>>>(ei, E, N);
    int nb = (N + 1023) / 1024;
    k_scan1<<<nb, 1024>>>(N);
    k_scan2<<<1, 128>>>(nb);
    k_scan3<<<(N + 1 + 1023) / 1024, 1024>>>(N, E);
    k_fill <<<(E + 255) / 256, 256>>>(ei, E, N);

    // ---- weight prep + x fp16 mirror ----
    k_prepW<<<192, 256>>>(W1l, W1r, W2l, W2r, W3l, W3r);
    int total4 = N * HDIM / 4;
    k_conv<<<(total4 + 255) / 256, 256>>>(x, total4);

    int aggBlocks   = (N * 32 + 255) / 256;
    int layerBlocks = (N + 127) / 128;

    // ---- layer 1: agg -> GEMM -> h1 fp32 + fp16 mirror ----
    k_agg      <<<aggBlocks, 256>>>(N);
    k_layer_mma<<<layerBlocks, 256>>>(b1, -1, 1, 0, 1, 0,
                                      (const float*)0, (const float*)0, (float*)0, N);

    // ---- layer 2: residual h1 -> h2 fp32 + fp16 mirror ----
    k_agg      <<<aggBlocks, 256>>>(N);
    k_layer_mma<<<layerBlocks, 256>>>(b2, 1, 2, 1, 1, 0,
                                      (const float*)0, (const float*)0, (float*)0, N);

    // ---- layer 3: residual h2, fused sigmoid head -> out ----
    k_agg      <<<aggBlocks, 256>>>(N);
    k_layer_mma<<<layerBlocks, 256>>>(b3, 2, 1, 2, 0, 1, Wo, bo, out, N);
}

// round 8
// speedup vs baseline: 2.6471x; 1.1006x over previous
#include <cuda_runtime.h>
#include <cuda_fp16.h>
#include <math.h>
#include <stdint.h>

#define NMAX 100000
#define EMAX 1600000
#define HDIM 128

// ---------------- scratch (device globals; referenced by name only) --------
__device__ __align__(16) __half g_m [NMAX * HDIM];   // aggregated max (fp16)
__device__ __align__(16) __half g_fh[NMAX * HDIM];   // current layer state (fp16)
__device__ int   g_deg[NMAX];
__device__ int   g_off[NMAX + 1];
__device__ int   g_cur[NMAX];
__device__ int   g_csr[EMAX];
__device__ int   g_bsum[128];
// fp16 weights in mma-ready layout: [3][8 kc][128 col][16 half2]
__device__ __align__(16) uint32_t g_Wh[3 * 8 * 128 * 16];

#define MMA_F16(d, a, b0v, b1v) \
    asm volatile( \
        "mma.sync.aligned.m16n8k16.row.col.f32.f16.f16.f32 " \
        "{%0,%1,%2,%3}, {%4,%5,%6,%7}, {%8,%9}, {%0,%1,%2,%3};" \
        : "+f"((d)[0]), "+f"((d)[1]), "+f"((d)[2]), "+f"((d)[3]) \
        : "r"((a)[0]), "r"((a)[1]), "r"((a)[2]), "r"((a)[3]), \
          "r"(b0v), "r"(b1v))

// ---------------- fused setup: deg=0, x->fp16 mirror, weight prep ----------
__global__ void k_setup(const float* __restrict__ x,
                        const float* __restrict__ W1l, const float* __restrict__ W1r,
                        const float* __restrict__ W2l, const float* __restrict__ W2r,
                        const float* __restrict__ W3l, const float* __restrict__ W3r,
                        int n, int total4) {
    int i = blockIdx.x * blockDim.x + threadIdx.x;
    if (i < total4) {
        float4 f = ((const float4*)x)[i];
        __half2 h0 = __floats2half2_rn(f.x, f.y);
        __half2 h1 = __floats2half2_rn(f.z, f.w);
        uint2 u;
        u.x = *(uint32_t*)&h0;
        u.y = *(uint32_t*)&h1;
        ((uint2*)g_fh)[i] = u;
    }
    if (i < n) g_deg[i] = 0;
    if (i < 3 * 8 * 128 * 16) {
        int widx = i >> 14;
        int rem  = i & 16383;
        int kc   = rem >> 11;
        int rem2 = rem & 2047;
        int col  = rem2 >> 4;
        int hp   = rem2 & 15;
        int k    = kc * 32 + hp * 2;
        const float* Wl = (widx == 0) ? W1l : (widx == 1) ? W2l : W3l;
        const float* Wr = (widx == 0) ? W1r : (widx == 1) ? W2r : W3r;
        float v0 = (k < HDIM)     ? Wl[col * HDIM + k]     : Wr[col * HDIM + k - HDIM];
        float v1 = (k + 1 < HDIM) ? Wl[col * HDIM + k + 1] : Wr[col * HDIM + k + 1 - HDIM];
        __half2 h = __floats2half2_rn(v0, v1);
        g_Wh[i] = *(uint32_t*)&h;
    }
}

// ---------------- CSR build ------------------------------------------------
__global__ void k_hist(const int* __restrict__ ei, int E, int n) {
    int e = blockIdx.x * blockDim.x + threadIdx.x;
    if (e < E) {
        int d = ei[E + e];
        if ((unsigned)d < (unsigned)n) atomicAdd(&g_deg[d], 1);
    }
}

__global__ void k_scan1(int n) {
    __shared__ int s[1024];
    int tid = threadIdx.x;
    int gid = blockIdx.x * 1024 + tid;
    int v = (gid < n) ? g_deg[gid] : 0;
    s[tid] = v;
    __syncthreads();
    for (int d = 1; d < 1024; d <<= 1) {
        int t = (tid >= d) ? s[tid - d] : 0;
        __syncthreads();
        s[tid] += t;
        __syncthreads();
    }
    if (gid < n) g_off[gid] = s[tid] - v;
    if (tid == 1023) g_bsum[blockIdx.x] = s[1023];
}

__global__ void k_scan2(int nb) {
    __shared__ int s[128];
    int tid = threadIdx.x;
    int v = (tid < nb) ? g_bsum[tid] : 0;
    s[tid] = v;
    __syncthreads();
    for (int d = 1; d < 128; d <<= 1) {
        int t = (tid >= d) ? s[tid - d] : 0;
        __syncthreads();
        s[tid] += t;
        __syncthreads();
    }
    if (tid < nb) g_bsum[tid] = s[tid] - v;   // exclusive
}

__global__ void k_scan3(int n, int E) {
    int gid = blockIdx.x * blockDim.x + threadIdx.x;
    if (gid < n) {
        int o = g_off[gid] + g_bsum[gid >> 10];
        g_off[gid] = o;
        g_cur[gid] = o;
    } else if (gid == n) {
        g_off[n] = E;
    }
}

__global__ void k_fill(const int* __restrict__ ei, int E, int n) {
    int e = blockIdx.x * blockDim.x + threadIdx.x;
    if (e < E) {
        int s = ei[e];
        int d = ei[E + e];
        if ((unsigned)s < (unsigned)n && (unsigned)d < (unsigned)n) {
            int pos = atomicAdd(&g_cur[d], 1);
            if ((unsigned)pos < (unsigned)E) g_csr[pos] = s;
        }
    }
}

// ---------------- per-node max aggregation (warp per node, fp16, MLP=4) ----
__global__ void k_agg(int n) {
    int w    = (blockIdx.x * blockDim.x + threadIdx.x) >> 5;
    int lane = threadIdx.x & 31;
    if (w >= n) return;
    int beg = g_off[w], end = g_off[w + 1];
    uint2 outv;
    if (beg < end) {
        const uint2* hv = (const uint2*)g_fh;
        const uint32_t NEG = 0xFBFFFBFFu;        // half2(-65504,-65504)
        __half2 a0 = *(const __half2*)&NEG;
        __half2 a1 = a0;
        int j = beg;
        for (; j + 3 < end; j += 4) {
            int s0 = g_csr[j],     s1 = g_csr[j + 1];
            int s2 = g_csr[j + 2], s3 = g_csr[j + 3];
            uint2 v0 = hv[(size_t)s0 * 32 + lane];
            uint2 v1 = hv[(size_t)s1 * 32 + lane];
            uint2 v2 = hv[(size_t)s2 * 32 + lane];
            uint2 v3 = hv[(size_t)s3 * 32 + lane];
            __half2 m01x = __hmax2(*(__half2*)&v0.x, *(__half2*)&v1.x);
            __half2 m23x = __hmax2(*(__half2*)&v2.x, *(__half2*)&v3.x);
            __half2 m01y = __hmax2(*(__half2*)&v0.y, *(__half2*)&v1.y);
            __half2 m23y = __hmax2(*(__half2*)&v2.y, *(__half2*)&v3.y);
            a0 = __hmax2(a0, __hmax2(m01x, m23x));
            a1 = __hmax2(a1, __hmax2(m01y, m23y));
        }
        for (; j < end; j++) {
            uint2 v0 = hv[(size_t)g_csr[j] * 32 + lane];
            a0 = __hmax2(a0, *(__half2*)&v0.x);
            a1 = __hmax2(a1, *(__half2*)&v0.y);
        }
        outv.x = *(uint32_t*)&a0;
        outv.y = *(uint32_t*)&a1;
    } else {
        outv.x = 0; outv.y = 0;   // empty segment -> 0 (PyG semantics)
    }
    ((uint2*)g_m)[(size_t)w * 32 + lane] = outv;
}

// ---------------- fp16 mma layer: GEMM + bias + ELU + residual (+head) -----
// new_h[i,:] = elu( [m|fh][i,:] @ Wcat^T + b ) (+ fh)  -> written back to fh
// fuse=1: instead of storing, compute sigmoid(h3 . Wo + bo) -> outv
#define FS_ST 20
#define WS_ST 20

__global__ void __launch_bounds__(256) k_layer_mma(
    const float* __restrict__ bias, int has_res, int wsel,
    int fuse,
    const float* __restrict__ Wo, const float* __restrict__ bo,
    float* __restrict__ outv, int n) {
    __shared__ __align__(16) uint32_t Fs[128 * FS_ST];
    __shared__ __align__(16) uint32_t Ws[128 * WS_ST];
    __shared__ float sPart[128 * 2];

    const uint32_t* wh = g_Wh + wsel * 16384;

    const int tid  = threadIdx.x;
    const int wid  = tid >> 5;
    const int lane = tid & 31;
    const int gi   = lane >> 2;
    const int ti   = lane & 3;
    const int wr   = wid & 3;     // rows wr*32..+31
    const int wc   = wid >> 2;    // cols wc*64..+63
    const int base = blockIdx.x * 128;

    const int s_node = tid >> 1;
    const int s_half = tid & 1;
    const int gn_row = base + s_node;

    float acc[2][8][4];
#pragma unroll
    for (int mt = 0; mt < 2; mt++)
#pragma unroll
        for (int nt = 0; nt < 8; nt++)
#pragma unroll
            for (int q = 0; q < 4; q++) acc[mt][nt][q] = 0.f;

    for (int kc = 0; kc < 8; kc++) {
        const __half* srcH = (kc < 4) ? g_m : g_fh;
        const int k0 = (kc & 3) * 32;
        __syncthreads();
        // B chunk: [128 col][16 half2] -> Ws stride 20
        {
            const uint4* bs = (const uint4*)(wh + kc * 2048);
#pragma unroll
            for (int r = 0; r < 2; r++) {
                int lin4 = r * 256 + tid;
                int col = lin4 >> 2, c4 = lin4 & 3;
                *(uint4*)&Ws[col * WS_ST + c4 * 4] = bs[lin4];
            }
        }
        // A chunk: fp16 rows, [128 node][16 half2] -> Fs stride 20
        {
            uint4 p0 = make_uint4(0, 0, 0, 0), p1 = p0;
            if (gn_row < n) {
                const __half* rp = srcH + (size_t)gn_row * HDIM + k0 + s_half * 16;
                p0 = *(const uint4*)rp;
                p1 = *(const uint4*)(rp + 8);
            }
            uint32_t* fd = &Fs[s_node * FS_ST + s_half * 8];
            *(uint4*)fd       = p0;
            *(uint4*)(fd + 4) = p1;
        }
        __syncthreads();

#pragma unroll
        for (int ks = 0; ks < 2; ks++) {
            const int kb = ks * 8;
            uint32_t a[2][4];
#pragma unroll
            for (int mt = 0; mt < 2; mt++) {
                int rb = wr * 32 + mt * 16;
                a[mt][0] = Fs[(rb + gi)     * FS_ST + kb + ti];
                a[mt][1] = Fs[(rb + 8 + gi) * FS_ST + kb + ti];
                a[mt][2] = Fs[(rb + gi)     * FS_ST + kb + ti + 4];
                a[mt][3] = Fs[(rb + 8 + gi) * FS_ST + kb + ti + 4];
            }
#pragma unroll
            for (int nt = 0; nt < 8; nt++) {
                int cb = wc * 64 + nt * 8 + gi;
                uint32_t b0 = Ws[cb * WS_ST + kb + ti];
                uint32_t b1 = Ws[cb * WS_ST + kb + ti + 4];
                MMA_F16(acc[0][nt], a[0], b0, b1);
                MMA_F16(acc[1][nt], a[1], b0, b1);
            }
        }
    }

    // ---------------- epilogue ----------------
    float part[2][2] = {{0.f, 0.f}, {0.f, 0.f}};
#pragma unroll
    for (int nt = 0; nt < 8; nt++) {
        int col = wc * 64 + nt * 8 + ti * 2;
        float bb0 = bias[col], bb1 = bias[col + 1];
        float wo0 = 0.f, wo1 = 0.f;
        if (fuse) { wo0 = Wo[col]; wo1 = Wo[col + 1]; }
#pragma unroll
        for (int mt = 0; mt < 2; mt++) {
#pragma unroll
            for (int half = 0; half < 2; half++) {
                int row = base + wr * 32 + mt * 16 + gi + half * 8;
                if (row >= n) continue;
                float v0 = acc[mt][nt][half * 2 + 0] + bb0;
                float v1 = acc[mt][nt][half * 2 + 1] + bb1;
                v0 = (v0 > 0.f) ? v0 : expm1f(v0);
                v1 = (v1 > 0.f) ? v1 : expm1f(v1);
                size_t o = (size_t)row * HDIM + col;
                if (has_res) {
                    __half2 rh = *(const __half2*)(g_fh + o);
                    float2 rr = __half22float2(rh);
                    v0 += rr.x; v1 += rr.y;
                }
                if (fuse) {
                    part[mt][half] += v0 * wo0 + v1 * wo1;
                } else {
                    __half2 hv = __floats2half2_rn(v0, v1);
                    *(__half2*)(g_fh + o) = hv;
                }
            }
        }
    }

    if (fuse) {
#pragma unroll
        for (int mt = 0; mt < 2; mt++)
#pragma unroll
            for (int half = 0; half < 2; half++) {
                float p = part[mt][half];
                p += __shfl_xor_sync(0xffffffff, p, 1);
                p += __shfl_xor_sync(0xffffffff, p, 2);
                if (ti == 0) {
                    int rl = wr * 32 + mt * 16 + gi + half * 8;
                    sPart[rl * 2 + wc] = p;
                }
            }
        __syncthreads();
        if (tid < 128) {
            int row = base + tid;
            if (row < n) {
                float z = sPart[tid * 2] + sPart[tid * 2 + 1] + bo[0];
                outv[row] = 1.f / (1.f + expf(-z));
            }
        }
    }
}

// ---------------- launcher (kernel launches ONLY) ---------------------------
extern "C" void kernel_launch(void* const* d_in, const int* in_sizes, int n_in,
                              void* d_out, int out_size) {
    const float* x   = (const float*)d_in[0];
    const int*   ei  = (const int*)d_in[1];     // edge_index is int32
    const float* W1l = (const float*)d_in[2];
    const float* b1  = (const float*)d_in[3];
    const float* W1r = (const float*)d_in[4];
    const float* W2l = (const float*)d_in[5];
    const float* b2  = (const float*)d_in[6];
    const float* W2r = (const float*)d_in[7];
    const float* W3l = (const float*)d_in[8];
    const float* b3  = (const float*)d_in[9];
    const float* W3r = (const float*)d_in[10];
    const float* Wo  = (const float*)d_in[11];
    const float* bo  = (const float*)d_in[12];
    float* out = (float*)d_out;

    int N = in_sizes[0] / HDIM;
    int E = in_sizes[1] / 2;
    if (N > NMAX) N = NMAX;
    if (E > EMAX) E = EMAX;

    int total4 = N * HDIM / 4;

    // ---- fused setup: deg=0, x->fp16, weight prep ----
    k_setup<<<(total4 + 255) / 256, 256>>>(x, W1l, W1r, W2l, W2r, W3l, W3r, N, total4);

    // ---- CSR build (dst-sorted adjacency) ----
    k_hist <<<(E + 255) / 256, 256>>>(ei, E, N);
    int nb = (N + 1023) / 1024;
    k_scan1<<<nb, 1024>>>(N);
    k_scan2<<<1, 128>>>(nb);
    k_scan3<<<(N + 1 + 1023) / 1024, 1024>>>(N, E);
    k_fill <<<(E + 255) / 256, 256>>>(ei, E, N);

    int aggBlocks   = (N * 32 + 255) / 256;
    int layerBlocks = (N + 127) / 128;

    // ---- layer 1: agg(x) -> GEMM -> fh = h1 ----
    k_agg      <<<aggBlocks, 256>>>(N);
    k_layer_mma<<<layerBlocks, 256>>>(b1, 0, 0, 0,
                                      (const float*)0, (const float*)0, (float*)0, N);

    // ---- layer 2: agg(h1) -> GEMM + residual -> fh = h2 ----
    k_agg      <<<aggBlocks, 256>>>(N);
    k_layer_mma<<<layerBlocks, 256>>>(b2, 1, 1, 0,
                                      (const float*)0, (const float*)0, (float*)0, N);

    // ---- layer 3: agg(h2) -> GEMM + residual + fused sigmoid head -> out ----
    k_agg      <<<aggBlocks, 256>>>(N);
    k_layer_mma<<<layerBlocks, 256>>>(b3, 1, 2, 1, Wo, bo, out, N);
}

// round 9
// speedup vs baseline: 2.8857x; 1.0901x over previous
#include <cuda_runtime.h>
#include <cuda_fp16.h>
#include <math.h>
#include <stdint.h>

#define NMAX 100000
#define EMAX 1600000
#define HDIM 128

// ---------------- scratch (device globals; referenced by name only) --------
__device__ __align__(16) __half g_m [NMAX * HDIM];   // aggregated max (fp16)
__device__ __align__(16) __half g_fh[NMAX * HDIM];   // current layer state (fp16)
__device__ int   g_deg[NMAX];
__device__ int   g_off[NMAX + 1];
__device__ int   g_cur[NMAX];
__device__ int   g_csr[EMAX];
__device__ int   g_bsum[128];
// fp16 weights in mma-ready layout: [3][8 kc][128 col][16 half2]
__device__ __align__(16) uint32_t g_Wh[3 * 8 * 128 * 16];

#define MMA_F16(d, a, b0v, b1v) \
    asm volatile( \
        "mma.sync.aligned.m16n8k16.row.col.f32.f16.f16.f32 " \
        "{%0,%1,%2,%3}, {%4,%5,%6,%7}, {%8,%9}, {%0,%1,%2,%3};" \
        : "+f"((d)[0]), "+f"((d)[1]), "+f"((d)[2]), "+f"((d)[3]) \
        : "r"((a)[0]), "r"((a)[1]), "r"((a)[2]), "r"((a)[3]), \
          "r"(b0v), "r"(b1v))

// ---------------- fused setup: deg=0, x->fp16 mirror, weight prep ----------
__global__ void k_setup(const float* __restrict__ x,
                        const float* __restrict__ W1l, const float* __restrict__ W1r,
                        const float* __restrict__ W2l, const float* __restrict__ W2r,
                        const float* __restrict__ W3l, const float* __restrict__ W3r,
                        int n, int total4) {
    int i = blockIdx.x * blockDim.x + threadIdx.x;
    if (i < total4) {
        float4 f = ((const float4*)x)[i];
        __half2 h0 = __floats2half2_rn(f.x, f.y);
        __half2 h1 = __floats2half2_rn(f.z, f.w);
        uint2 u;
        u.x = *(uint32_t*)&h0;
        u.y = *(uint32_t*)&h1;
        ((uint2*)g_fh)[i] = u;
    }
    if (i < n) g_deg[i] = 0;
    if (i < 3 * 8 * 128 * 16) {
        int widx = i >> 14;
        int rem  = i & 16383;
        int kc   = rem >> 11;
        int rem2 = rem & 2047;
        int col  = rem2 >> 4;
        int hp   = rem2 & 15;
        int k    = kc * 32 + hp * 2;
        const float* Wl = (widx == 0) ? W1l : (widx == 1) ? W2l : W3l;
        const float* Wr = (widx == 0) ? W1r : (widx == 1) ? W2r : W3r;
        float v0 = (k < HDIM)     ? Wl[col * HDIM + k]     : Wr[col * HDIM + k - HDIM];
        float v1 = (k + 1 < HDIM) ? Wl[col * HDIM + k + 1] : Wr[col * HDIM + k + 1 - HDIM];
        __half2 h = __floats2half2_rn(v0, v1);
        g_Wh[i] = *(uint32_t*)&h;
    }
}

// ---------------- CSR build ------------------------------------------------
__global__ void k_hist(const int* __restrict__ ei, int E, int n) {
    int e = blockIdx.x * blockDim.x + threadIdx.x;
    if (e < E) {
        int d = ei[E + e];
        if ((unsigned)d < (unsigned)n) atomicAdd(&g_deg[d], 1);
    }
}

__global__ void k_scan1(int n) {
    __shared__ int s[1024];
    int tid = threadIdx.x;
    int gid = blockIdx.x * 1024 + tid;
    int v = (gid < n) ? g_deg[gid] : 0;
    s[tid] = v;
    __syncthreads();
    for (int d = 1; d < 1024; d <<= 1) {
        int t = (tid >= d) ? s[tid - d] : 0;
        __syncthreads();
        s[tid] += t;
        __syncthreads();
    }
    if (gid < n) g_off[gid] = s[tid] - v;
    if (tid == 1023) g_bsum[blockIdx.x] = s[1023];
}

__global__ void k_scan2(int nb) {
    __shared__ int s[128];
    int tid = threadIdx.x;
    int v = (tid < nb) ? g_bsum[tid] : 0;
    s[tid] = v;
    __syncthreads();
    for (int d = 1; d < 128; d <<= 1) {
        int t = (tid >= d) ? s[tid - d] : 0;
        __syncthreads();
        s[tid] += t;
        __syncthreads();
    }
    if (tid < nb) g_bsum[tid] = s[tid] - v;   // exclusive
}

__global__ void k_scan3(int n, int E) {
    int gid = blockIdx.x * blockDim.x + threadIdx.x;
    if (gid < n) {
        int o = g_off[gid] + g_bsum[gid >> 10];
        g_off[gid] = o;
        g_cur[gid] = o;
    } else if (gid == n) {
        g_off[n] = E;
    }
}

__global__ void k_fill(const int* __restrict__ ei, int E, int n) {
    int e = blockIdx.x * blockDim.x + threadIdx.x;
    if (e < E) {
        int s = ei[e];
        int d = ei[E + e];
        if ((unsigned)s < (unsigned)n && (unsigned)d < (unsigned)n) {
            int pos = atomicAdd(&g_cur[d], 1);
            if ((unsigned)pos < (unsigned)E) g_csr[pos] = s;
        }
    }
}

// ---------------- per-node max aggregation (2 nodes/warp, uint4 lanes) -----
__global__ void k_agg(int n) {
    int gw   = (blockIdx.x * blockDim.x + threadIdx.x) >> 5;
    int lane = threadIdx.x & 31;
    int w    = gw * 2 + (lane >> 4);
    int l16  = lane & 15;
    if (w >= n) return;
    int beg = g_off[w], end = g_off[w + 1];
    uint4 outv;
    if (beg < end) {
        const uint4* hv = (const uint4*)g_fh;    // row = 16 uint4
        const uint32_t NEG = 0xFBFFFBFFu;        // half2(-65504,-65504)
        __half2 a0 = *(const __half2*)&NEG;
        __half2 a1 = a0, a2 = a0, a3 = a0;
        int j = beg;
        for (; j + 3 < end; j += 4) {
            int s0 = g_csr[j],     s1 = g_csr[j + 1];
            int s2 = g_csr[j + 2], s3 = g_csr[j + 3];
            uint4 v0 = hv[(size_t)s0 * 16 + l16];
            uint4 v1 = hv[(size_t)s1 * 16 + l16];
            uint4 v2 = hv[(size_t)s2 * 16 + l16];
            uint4 v3 = hv[(size_t)s3 * 16 + l16];
            __half2 mx0 = __hmax2(__hmax2(*(__half2*)&v0.x, *(__half2*)&v1.x),
                                  __hmax2(*(__half2*)&v2.x, *(__half2*)&v3.x));
            __half2 mx1 = __hmax2(__hmax2(*(__half2*)&v0.y, *(__half2*)&v1.y),
                                  __hmax2(*(__half2*)&v2.y, *(__half2*)&v3.y));
            __half2 mx2 = __hmax2(__hmax2(*(__half2*)&v0.z, *(__half2*)&v1.z),
                                  __hmax2(*(__half2*)&v2.z, *(__half2*)&v3.z));
            __half2 mx3 = __hmax2(__hmax2(*(__half2*)&v0.w, *(__half2*)&v1.w),
                                  __hmax2(*(__half2*)&v2.w, *(__half2*)&v3.w));
            a0 = __hmax2(a0, mx0);
            a1 = __hmax2(a1, mx1);
            a2 = __hmax2(a2, mx2);
            a3 = __hmax2(a3, mx3);
        }
        for (; j < end; j++) {
            uint4 v0 = hv[(size_t)g_csr[j] * 16 + l16];
            a0 = __hmax2(a0, *(__half2*)&v0.x);
            a1 = __hmax2(a1, *(__half2*)&v0.y);
            a2 = __hmax2(a2, *(__half2*)&v0.z);
            a3 = __hmax2(a3, *(__half2*)&v0.w);
        }
        outv.x = *(uint32_t*)&a0;
        outv.y = *(uint32_t*)&a1;
        outv.z = *(uint32_t*)&a2;
        outv.w = *(uint32_t*)&a3;
    } else {
        outv = make_uint4(0, 0, 0, 0);   // empty segment -> 0 (PyG semantics)
    }
    ((uint4*)g_m)[(size_t)w * 16 + l16] = outv;
}

// ---------------- fp16 mma layer: GEMM + bias + ELU + residual (+head) -----
// new_h[i,:] = elu( [m|fh][i,:] @ Wcat^T + b ) (+ fh)  -> written back to fh
// fuse=1: instead of storing, compute sigmoid(h3 . Wo + bo) -> outv
#define FS_ST 20
#define WS_ST 20

__global__ void __launch_bounds__(256, 2) k_layer_mma(
    const float* __restrict__ bias, int has_res, int wsel,
    int fuse,
    const float* __restrict__ Wo, const float* __restrict__ bo,
    float* __restrict__ outv, int n) {
    __shared__ __align__(16) uint32_t Fs[128 * FS_ST];
    __shared__ __align__(16) uint32_t Ws[128 * WS_ST];
    __shared__ float sPart[128 * 2];

    const uint32_t* wh = g_Wh + wsel * 16384;

    const int tid  = threadIdx.x;
    const int wid  = tid >> 5;
    const int lane = tid & 31;
    const int gi   = lane >> 2;
    const int ti   = lane & 3;
    const int wr   = wid & 3;     // rows wr*32..+31
    const int wc   = wid >> 2;    // cols wc*64..+63
    const int base = blockIdx.x * 128;

    const int s_node = tid >> 1;
    const int s_half = tid & 1;
    const int gn_row = base + s_node;

    float acc[2][8][4];
#pragma unroll
    for (int mt = 0; mt < 2; mt++)
#pragma unroll
        for (int nt = 0; nt < 8; nt++)
#pragma unroll
            for (int q = 0; q < 4; q++) acc[mt][nt][q] = 0.f;

    uint4 pb0, pb1, pa0, pa1;
    // prefetch chunk 0
    {
        const uint4* bs = (const uint4*)(wh);
        pb0 = bs[tid];
        pb1 = bs[256 + tid];
        pa0 = make_uint4(0, 0, 0, 0); pa1 = pa0;
        if (gn_row < n) {
            const __half* rp = g_m + (size_t)gn_row * HDIM + s_half * 16;
            pa0 = *(const uint4*)rp;
            pa1 = *(const uint4*)(rp + 8);
        }
    }

    for (int kc = 0; kc < 8; kc++) {
        __syncthreads();   // smem free (prev chunk consumed)
        // store prefetched chunk
        {
            int col0 = tid >> 2, c40 = tid & 3;
            *(uint4*)&Ws[col0 * WS_ST + c40 * 4] = pb0;
            int lin1 = 256 + tid;
            int col1 = lin1 >> 2, c41 = lin1 & 3;
            *(uint4*)&Ws[col1 * WS_ST + c41 * 4] = pb1;
            uint32_t* fd = &Fs[s_node * FS_ST + s_half * 8];
            *(uint4*)fd       = pa0;
            *(uint4*)(fd + 4) = pa1;
        }
        __syncthreads();   // smem ready

        // prefetch next chunk (latency overlaps MMA below)
        if (kc < 7) {
            int kn = kc + 1;
            const uint4* bs = (const uint4*)(wh + kn * 2048);
            pb0 = bs[tid];
            pb1 = bs[256 + tid];
            const __half* srcH = (kn < 4) ? g_m : g_fh;
            int k0 = (kn & 3) * 32;
            pa0 = make_uint4(0, 0, 0, 0); pa1 = pa0;
            if (gn_row < n) {
                const __half* rp = srcH + (size_t)gn_row * HDIM + k0 + s_half * 16;
                pa0 = *(const uint4*)rp;
                pa1 = *(const uint4*)(rp + 8);
            }
        }

#pragma unroll
        for (int ks = 0; ks < 2; ks++) {
            const int kb = ks * 8;
            uint32_t a[2][4];
#pragma unroll
            for (int mt = 0; mt < 2; mt++) {
                int rb = wr * 32 + mt * 16;
                a[mt][0] = Fs[(rb + gi)     * FS_ST + kb + ti];
                a[mt][1] = Fs[(rb + 8 + gi) * FS_ST + kb + ti];
                a[mt][2] = Fs[(rb + gi)     * FS_ST + kb + ti + 4];
                a[mt][3] = Fs[(rb + 8 + gi) * FS_ST + kb + ti + 4];
            }
#pragma unroll
            for (int nt = 0; nt < 8; nt++) {
                int cb = wc * 64 + nt * 8 + gi;
                uint32_t b0 = Ws[cb * WS_ST + kb + ti];
                uint32_t b1 = Ws[cb * WS_ST + kb + ti + 4];
                MMA_F16(acc[0][nt], a[0], b0, b1);
                MMA_F16(acc[1][nt], a[1], b0, b1);
            }
        }
    }

    // ---------------- epilogue ----------------
    float part[2][2] = {{0.f, 0.f}, {0.f, 0.f}};
#pragma unroll
    for (int nt = 0; nt < 8; nt++) {
        int col = wc * 64 + nt * 8 + ti * 2;
        float bb0 = bias[col], bb1 = bias[col + 1];
        float wo0 = 0.f, wo1 = 0.f;
        if (fuse) { wo0 = Wo[col]; wo1 = Wo[col + 1]; }
#pragma unroll
        for (int mt = 0; mt < 2; mt++) {
#pragma unroll
            for (int half = 0; half < 2; half++) {
                int row = base + wr * 32 + mt * 16 + gi + half * 8;
                if (row >= n) continue;
                float v0 = acc[mt][nt][half * 2 + 0] + bb0;
                float v1 = acc[mt][nt][half * 2 + 1] + bb1;
                v0 = (v0 > 0.f) ? v0 : expm1f(v0);
                v1 = (v1 > 0.f) ? v1 : expm1f(v1);
                size_t o = (size_t)row * HDIM + col;
                if (has_res) {
                    __half2 rh = *(const __half2*)(g_fh + o);
                    float2 rr = __half22float2(rh);
                    v0 += rr.x; v1 += rr.y;
                }
                if (fuse) {
                    part[mt][half] += v0 * wo0 + v1 * wo1;
                } else {
                    __half2 hv = __floats2half2_rn(v0, v1);
                    *(__half2*)(g_fh + o) = hv;
                }
            }
        }
    }

    if (fuse) {
#pragma unroll
        for (int mt = 0; mt < 2; mt++)
#pragma unroll
            for (int half = 0; half < 2; half++) {
                float p = part[mt][half];
                p += __shfl_xor_sync(0xffffffff, p, 1);
                p += __shfl_xor_sync(0xffffffff, p, 2);
                if (ti == 0) {
                    int rl = wr * 32 + mt * 16 + gi + half * 8;
                    sPart[rl * 2 + wc] = p;
                }
            }
        __syncthreads();
        if (tid < 128) {
            int row = base + tid;
            if (row < n) {
                float z = sPart[tid * 2] + sPart[tid * 2 + 1] + bo[0];
                outv[row] = 1.f / (1.f + expf(-z));
            }
        }
    }
}

// ---------------- launcher (kernel launches ONLY) ---------------------------
extern "C" void kernel_launch(void* const* d_in, const int* in_sizes, int n_in,
                              void* d_out, int out_size) {
    const float* x   = (const float*)d_in[0];
    const int*   ei  = (const int*)d_in[1];     // edge_index is int32
    const float* W1l = (const float*)d_in[2];
    const float* b1  = (const float*)d_in[3];
    const float* W1r = (const float*)d_in[4];
    const float* W2l = (const float*)d_in[5];
    const float* b2  = (const float*)d_in[6];
    const float* W2r = (const float*)d_in[7];
    const float* W3l = (const float*)d_in[8];
    const float* b3  = (const float*)d_in[9];
    const float* W3r = (const float*)d_in[10];
    const float* Wo  = (const float*)d_in[11];
    const float* bo  = (const float*)d_in[12];
    float* out = (float*)d_out;

    int N = in_sizes[0] / HDIM;
    int E = in_sizes[1] / 2;
    if (N > NMAX) N = NMAX;
    if (E > EMAX) E = EMAX;

    int total4 = N * HDIM / 4;

    // ---- fused setup: deg=0, x->fp16, weight prep ----
    k_setup<<<(total4 + 255) / 256, 256>>>(x, W1l, W1r, W2l, W2r, W3l, W3r, N, total4);

    // ---- CSR build (dst-sorted adjacency) ----
    k_hist <<<(E + 255) / 256, 256>>>(ei, E, N);
    int nb = (N + 1023) / 1024;
    k_scan1<<<nb, 1024>>>(N);
    k_scan2<<<1, 128>>>(nb);
    k_scan3<<<(N + 1 + 1023) / 1024, 1024>>>(N, E);
    k_fill <<<(E + 255) / 256, 256>>>(ei, E, N);

    int aggBlocks   = (N * 16 + 255) / 256;
    int layerBlocks = (N + 127) / 128;

    // ---- layer 1: agg(x) -> GEMM -> fh = h1 ----
    k_agg      <<<aggBlocks, 256>>>(N);
    k_layer_mma<<<layerBlocks, 256>>>(b1, 0, 0, 0,
                                      (const float*)0, (const float*)0, (float*)0, N);

    // ---- layer 2: agg(h1) -> GEMM + residual -> fh = h2 ----
    k_agg      <<<aggBlocks, 256>>>(N);
    k_layer_mma<<<layerBlocks, 256>>>(b2, 1, 1, 0,
                                      (const float*)0, (const float*)0, (float*)0, N);

    // ---- layer 3: agg(h2) -> GEMM + residual + fused sigmoid head -> out ----
    k_agg      <<<aggBlocks, 256>>>(N);
    k_layer_mma<<<layerBlocks, 256>>>(b3, 1, 2, 1, Wo, bo, out, N);
}